// round 16
// baseline (speedup 1.0000x reference)
#include <cuda_runtime.h>
#include <cuda_fp16.h>
#include <math.h>
#include <stdint.h>

#define BATCH 4
#define SEQ   1024
#define DIM   1024
#define HEADS 16
#define HD    64
#define MLPD  4096
#define DEPTH 4
#define MROWS (BATCH*SEQ)          // 4096
#define ATT_SCALE (1.0f/32.0f)     // DIM^-0.5

// ------------------- scratch (no allocation allowed) -------------------
__device__ __half g_h   [MROWS*DIM];
__device__ __half g_qkv [MROWS*3*DIM];
__device__ __half g_o   [MROWS*DIM];
__device__ __half g_mlp [MROWS*MLPD];
// transposed (N-major) fp16 weights
__device__ __half g_wt_qkv[DEPTH*3*DIM*DIM];
__device__ __half g_wt_out[DEPTH*DIM*DIM];
__device__ __half g_wt1   [DEPTH*MLPD*DIM];
__device__ __half g_wt2   [DEPTH*DIM*MLPD];

// ------------------- helpers -------------------
__device__ __forceinline__ uint32_t smem_u32(const void* p) {
    uint32_t a;
    asm("{ .reg .u64 t; cvta.to.shared.u64 t, %1; cvt.u32.u64 %0, t; }" : "=r"(a) : "l"(p));
    return a;
}
static __device__ __forceinline__ uint32_t sw128(uint32_t off) {
    return off ^ ((off >> 3) & 0x70);
}
__device__ __forceinline__ void ldsm4(uint32_t& d0, uint32_t& d1, uint32_t& d2,
                                      uint32_t& d3, uint32_t addr) {
    asm volatile("ldmatrix.sync.aligned.m8n8.x4.shared.b16 {%0,%1,%2,%3}, [%4];"
                 : "=r"(d0), "=r"(d1), "=r"(d2), "=r"(d3) : "r"(addr));
}
__device__ __forceinline__ void ldsm4t(uint32_t& d0, uint32_t& d1, uint32_t& d2,
                                       uint32_t& d3, uint32_t addr) {
    asm volatile("ldmatrix.sync.aligned.m8n8.x4.trans.shared.b16 {%0,%1,%2,%3}, [%4];"
                 : "=r"(d0), "=r"(d1), "=r"(d2), "=r"(d3) : "r"(addr));
}
__device__ __forceinline__ void mma_f16(float* c, const uint32_t* a,
                                        uint32_t b0, uint32_t b1) {
    asm volatile(
        "mma.sync.aligned.m16n8k16.row.col.f32.f16.f16.f32 "
        "{%0,%1,%2,%3}, {%4,%5,%6,%7}, {%8,%9}, {%0,%1,%2,%3};"
        : "+f"(c[0]), "+f"(c[1]), "+f"(c[2]), "+f"(c[3])
        : "r"(a[0]), "r"(a[1]), "r"(a[2]), "r"(a[3]), "r"(b0), "r"(b1));
}
__device__ __forceinline__ void cp_async16(uint32_t dst, const void* src) {
    asm volatile("cp.async.ca.shared.global [%0], [%1], 16;"
                 :: "r"(dst), "l"(src) : "memory");
}
#define CP_COMMIT() asm volatile("cp.async.commit_group;" ::: "memory")
#define CP_WAIT(n)  asm volatile("cp.async.wait_group %0;" :: "n"(n) : "memory")

// ------------------- LayerNorm: one warp per row --------
__global__ void ln_kernel(const float* __restrict__ x, const float* __restrict__ g,
                          const float* __restrict__ b, __half* __restrict__ out) {
    int row  = blockIdx.x * 8 + (threadIdx.x >> 5);
    int lane = threadIdx.x & 31;
    const float* xr = x + (size_t)row * DIM;

    float4 v[8];
    float s = 0.f, s2 = 0.f;
#pragma unroll
    for (int i = 0; i < 8; i++) {
        v[i] = *(const float4*)(xr + 4 * (lane + i * 32));
        s  += v[i].x + v[i].y + v[i].z + v[i].w;
        s2 += v[i].x * v[i].x + v[i].y * v[i].y + v[i].z * v[i].z + v[i].w * v[i].w;
    }
#pragma unroll
    for (int o = 16; o > 0; o >>= 1) {
        s  += __shfl_xor_sync(0xffffffffu, s,  o);
        s2 += __shfl_xor_sync(0xffffffffu, s2, o);
    }
    float mean = s * (1.0f / DIM);
    float rstd = rsqrtf(s2 * (1.0f / DIM) - mean * mean + 1e-5f);

    __half* orow = out + (size_t)row * DIM;
#pragma unroll
    for (int i = 0; i < 8; i++) {
        int c = 4 * (lane + i * 32);
        float4 gv = *(const float4*)(g + c);
        float4 bv = *(const float4*)(b + c);
        __half2 h0 = __floats2half2_rn((v[i].x - mean) * rstd * gv.x + bv.x,
                                       (v[i].y - mean) * rstd * gv.y + bv.y);
        __half2 h1 = __floats2half2_rn((v[i].z - mean) * rstd * gv.z + bv.z,
                                       (v[i].w - mean) * rstd * gv.w + bv.w);
        *(__half2*)(orow + c)     = h0;
        *(__half2*)(orow + c + 2) = h1;
    }
}

// --------- weight transpose to fp16: Wt[n][k] = h(W[k][n]) ------------------
__global__ void transpose_h(const float* __restrict__ Wb, __half* __restrict__ Wtb,
                            int K, int N) {
    __shared__ float t[64][65];
    const float* W  = Wb  + (size_t)blockIdx.z * K * N;
    __half* Wt      = Wtb + (size_t)blockIdx.z * K * N;
    int bn = blockIdx.x * 64, bk = blockIdx.y * 64;
    int tid = threadIdx.x;
    int rk = tid >> 4;
    int cn = (tid & 15) << 2;
#pragma unroll
    for (int i = 0; i < 4; i++) {
        int k = rk + i * 16;
        float4 v = *(const float4*)(W + (size_t)(bk + k) * N + bn + cn);
        t[cn + 0][k] = v.x;
        t[cn + 1][k] = v.y;
        t[cn + 2][k] = v.z;
        t[cn + 3][k] = v.w;
    }
    __syncthreads();
    int rn = tid >> 2;
    int ck = (tid & 3) << 4;
    __half hv[16];
#pragma unroll
    for (int j = 0; j < 16; j++) hv[j] = __float2half_rn(t[rn][ck + j]);
    *(float4*)(Wt + (size_t)(bn + rn) * K + bk + ck)     = *(float4*)&hv[0];
    *(float4*)(Wt + (size_t)(bn + rn) * K + bk + ck + 8) = *(float4*)&hv[8];
}

// ------------------- fp16 mma GEMM (verified champion, unchanged) ----------
#define GM_BUF 16384
#define GM_SMEM (4 * GM_BUF + 1024)

template<int EPI>  // 0 plain->half, 2 bias+gelu->half, 3 bias+residual->float
__global__ __launch_bounds__(128, 2)
void gemm_mma(const __half* __restrict__ A, const __half* __restrict__ Bt,
              const float* __restrict__ bias, const float* __restrict__ res,
              void* __restrict__ Cv, int K, int Ndim) {
    extern __shared__ char smraw[];
    uint32_t sbase = (smem_u32(smraw) + 1023u) & ~1023u;

    int tid = threadIdx.x;
    int wid = tid >> 5, lane = tid & 31;
    int wm = wid & 1, wn = wid >> 1;       // 2x2 warp grid
    int brow = blockIdx.y << 7, bcol = blockIdx.x << 7;
    int g = lane >> 3, r = lane & 7;

    float acc[4][8][4];
#pragma unroll
    for (int i = 0; i < 4; i++)
#pragma unroll
        for (int j = 0; j < 8; j++)
#pragma unroll
            for (int q = 0; q < 4; q++) acc[i][j][q] = 0.f;

    const int KT = K >> 6;
    int arow = tid >> 3, ack = tid & 7;

    auto issue_tile = [&](uint32_t dstbase, const __half* src) {
#pragma unroll
        for (int i = 0; i < 8; i++) {
            int rr = arow + i * 16;
            cp_async16(dstbase + sw128((uint32_t)(rr * 128 + (ack << 4))),
                       src + (size_t)rr * K + (ack << 3));
        }
    };

    issue_tile(sbase, A + (size_t)brow * K);
    issue_tile(sbase + 2 * GM_BUF, Bt + (size_t)bcol * K);
    CP_COMMIT();

    for (int kt = 0; kt < KT; kt++) {
        int b = kt & 1;
        uint32_t Ab_s = sbase + b * GM_BUF;
        uint32_t Bb_s = sbase + 2 * GM_BUF + b * GM_BUF;

        CP_WAIT(0);
        __syncthreads();

        if (kt + 1 < KT) {
            int nb = b ^ 1;
            issue_tile(sbase + nb * GM_BUF,
                       A + (size_t)brow * K + ((kt + 1) << 6));
            issue_tile(sbase + 2 * GM_BUF + nb * GM_BUF,
                       Bt + (size_t)bcol * K + ((kt + 1) << 6));
            CP_COMMIT();
        }

#pragma unroll
        for (int ks = 0; ks < 4; ks++) {
            uint32_t afr[4][4];
#pragma unroll
            for (int im = 0; im < 4; im++) {
                int rowa = wm * 64 + im * 16 + r + (g & 1) * 8;
                uint32_t ck = (uint32_t)(ks * 2 + (g >> 1));
                ldsm4(afr[im][0], afr[im][1], afr[im][2], afr[im][3],
                      Ab_s + sw128((uint32_t)(rowa * 128) + (ck << 4)));
            }
            uint32_t bfr[8][2];
#pragma unroll
            for (int ip = 0; ip < 4; ip++) {
                int rowb = wn * 64 + ip * 16 + (g >> 1) * 8 + r;
                uint32_t ck = (uint32_t)(ks * 2 + (g & 1));
                ldsm4(bfr[2 * ip][0], bfr[2 * ip][1], bfr[2 * ip + 1][0], bfr[2 * ip + 1][1],
                      Bb_s + sw128((uint32_t)(rowb * 128) + (ck << 4)));
            }
#pragma unroll
            for (int im = 0; im < 4; im++)
#pragma unroll
                for (int in = 0; in < 8; in++)
                    mma_f16(acc[im][in], afr[im], bfr[in][0], bfr[in][1]);
        }
    }

    int lr = lane >> 2, lc = (lane & 3) << 1;
#pragma unroll
    for (int im = 0; im < 4; im++) {
#pragma unroll
        for (int half_ = 0; half_ < 2; half_++) {
            int row = brow + wm * 64 + im * 16 + lr + half_ * 8;
            const float* Rrow = (EPI == 3) ? (res + (size_t)row * Ndim) : nullptr;
#pragma unroll
            for (int in = 0; in < 8; in++) {
                int col = bcol + wn * 64 + in * 8 + lc;
                float u0 = acc[im][in][half_ * 2 + 0];
                float u1 = acc[im][in][half_ * 2 + 1];
                if (EPI >= 2) { u0 += bias[col]; u1 += bias[col + 1]; }
                if (EPI == 2) {
                    u0 = 0.5f * u0 * (1.0f + erff(u0 * 0.70710678118654752f));
                    u1 = 0.5f * u1 * (1.0f + erff(u1 * 0.70710678118654752f));
                }
                if (EPI == 3) {
                    float* Crow = (float*)Cv + (size_t)row * Ndim;
                    *(float2*)(Crow + col) = make_float2(u0 + Rrow[col], u1 + Rrow[col + 1]);
                } else {
                    __half* Crow = (__half*)Cv + (size_t)row * Ndim;
                    *(__half2*)(Crow + col) = __floats2half2_rn(u0, u1);
                }
            }
        }
    }
}

// ------------------- fp16 tensor-core flash attention (champion) -----------
#define A_SQ  0                    // 16384
#define A_SK  16384                // 2 x 8192
#define A_SV  32768                // 2 x 8192
#define A_SP  49152                // 16384
#define A_SMEM (65536 + 1024)

__global__ __launch_bounds__(128, 2)
void attn_mma(const __half* __restrict__ qkv, __half* __restrict__ o) {
    extern __shared__ char smraw[];
    uint32_t sraw = smem_u32(smraw);
    uint32_t sb = (sraw + 1023u) & ~1023u;
    char* smb = smraw + (sb - sraw);

    int tid = threadIdx.x;
    int w = tid >> 5, lane = tid & 31;
    int g = lane >> 3, r = lane & 7;
    int lr = lane >> 2, lc = lane & 3;

    int bh = blockIdx.y;
    int b = bh >> 4, h = bh & 15;
    int q0 = blockIdx.x << 7;
    const __half* gq = qkv + (size_t)b * SEQ * 3 * DIM + h * HD;
    const __half* gk = gq + DIM;
    const __half* gv = gq + 2 * DIM;

    auto issue_kv = [&](int st, int kt) {
#pragma unroll
        for (int i = 0; i < 4; i++) {
            int idx = tid + i * 128;
            int row = idx >> 3, ck = idx & 7;
            cp_async16(sb + A_SK + st * 8192 + sw128((uint32_t)(row * 128 + (ck << 4))),
                       gk + (size_t)(kt + row) * (3 * DIM) + (ck << 3));
            cp_async16(sb + A_SV + st * 8192 + sw128((uint32_t)(row * 128 + (ck << 4))),
                       gv + (size_t)(kt + row) * (3 * DIM) + (ck << 3));
        }
    };

    // ---- Q tile 128x64h ----
#pragma unroll
    for (int i = 0; i < 8; i++) {
        int idx = tid + i * 128;
        int row = idx >> 3, ck = idx & 7;
        cp_async16(sb + A_SQ + sw128((uint32_t)(row * 128 + (ck << 4))),
                   gq + (size_t)(q0 + row) * (3 * DIM) + (ck << 3));
    }
    CP_COMMIT();
    issue_kv(0, 0);
    CP_COMMIT();

    // ---- hoist Q fragments (loop-invariant) ----
    CP_WAIT(1);
    __syncthreads();
    uint32_t qfr[4][2][4];
#pragma unroll
    for (int ks = 0; ks < 4; ks++)
#pragma unroll
        for (int im = 0; im < 2; im++) {
            int rowa = w * 32 + im * 16 + r + (g & 1) * 8;
            ldsm4(qfr[ks][im][0], qfr[ks][im][1], qfr[ks][im][2], qfr[ks][im][3],
                  sb + A_SQ + sw128((uint32_t)(rowa * 128) +
                                    (uint32_t)((ks * 2 + (g >> 1)) << 4)));
        }

    float m0[2], m1[2], l0[2], l1[2];
    float oacc[2][8][4];
#pragma unroll
    for (int im = 0; im < 2; im++) {
        m0[im] = -1e30f; m1[im] = -1e30f; l0[im] = 0.f; l1[im] = 0.f;
#pragma unroll
        for (int j = 0; j < 8; j++)
#pragma unroll
            for (int q = 0; q < 4; q++) oacc[im][j][q] = 0.f;
    }

    const int NT = SEQ / 64;
    for (int kti = 0; kti < NT; kti++) {
        int st = kti & 1;
        uint32_t Ks = sb + A_SK + st * 8192;
        uint32_t Vs = sb + A_SV + st * 8192;

        if (kti + 1 < NT) {
            issue_kv(st ^ 1, (kti + 1) * 64);
            CP_COMMIT();
            CP_WAIT(1);
        } else {
            CP_WAIT(0);
        }
        __syncthreads();

        // ---- S = Q K^T ----
        float sacc[2][8][4];
#pragma unroll
        for (int im = 0; im < 2; im++)
#pragma unroll
            for (int j = 0; j < 8; j++)
#pragma unroll
                for (int q = 0; q < 4; q++) sacc[im][j][q] = 0.f;

#pragma unroll
        for (int ks = 0; ks < 4; ks++) {
            uint32_t bfr[8][2];
#pragma unroll
            for (int ip = 0; ip < 4; ip++) {
                int rowb = ip * 16 + (g >> 1) * 8 + r;
                ldsm4(bfr[2 * ip][0], bfr[2 * ip][1], bfr[2 * ip + 1][0], bfr[2 * ip + 1][1],
                      Ks + sw128((uint32_t)(rowb * 128) +
                                 (uint32_t)((ks * 2 + (g & 1)) << 4)));
            }
#pragma unroll
            for (int im = 0; im < 2; im++)
#pragma unroll
                for (int j = 0; j < 8; j++)
                    mma_f16(sacc[im][j], qfr[ks][im], bfr[j][0], bfr[j][1]);
        }

        // ---- online softmax ----
#pragma unroll
        for (int im = 0; im < 2; im++) {
            float rm0 = -1e30f, rm1 = -1e30f;
#pragma unroll
            for (int j = 0; j < 8; j++) {
                rm0 = fmaxf(rm0, fmaxf(sacc[im][j][0], sacc[im][j][1]));
                rm1 = fmaxf(rm1, fmaxf(sacc[im][j][2], sacc[im][j][3]));
            }
            rm0 *= ATT_SCALE; rm1 *= ATT_SCALE;
#pragma unroll
            for (int off = 1; off < 4; off <<= 1) {
                rm0 = fmaxf(rm0, __shfl_xor_sync(0xffffffffu, rm0, off));
                rm1 = fmaxf(rm1, __shfl_xor_sync(0xffffffffu, rm1, off));
            }
            float nm0 = fmaxf(m0[im], rm0), nm1 = fmaxf(m1[im], rm1);
            float corr0 = __expf(m0[im] - nm0), corr1 = __expf(m1[im] - nm1);
            m0[im] = nm0; m1[im] = nm1;
            float ls0 = 0.f, ls1 = 0.f;
            int prow0 = w * 32 + im * 16 + lr;
#pragma unroll
            for (int j = 0; j < 8; j++) {
                __half2 hp0 = __floats2half2_rn(__expf(sacc[im][j][0] * ATT_SCALE - nm0),
                                                __expf(sacc[im][j][1] * ATT_SCALE - nm0));
                __half2 hp1 = __floats2half2_rn(__expf(sacc[im][j][2] * ATT_SCALE - nm1),
                                                __expf(sacc[im][j][3] * ATT_SCALE - nm1));
                float2 f0 = __half22float2(hp0), f1 = __half22float2(hp1);
                ls0 += f0.x + f0.y; ls1 += f1.x + f1.y;
                uint32_t cb = (uint32_t)((j * 8 + 2 * lc) << 1);
                *(__half2*)(smb + A_SP + sw128((uint32_t)(prow0 * 128) + cb)) = hp0;
                *(__half2*)(smb + A_SP + sw128((uint32_t)((prow0 + 8) * 128) + cb)) = hp1;
            }
#pragma unroll
            for (int off = 1; off < 4; off <<= 1) {
                ls0 += __shfl_xor_sync(0xffffffffu, ls0, off);
                ls1 += __shfl_xor_sync(0xffffffffu, ls1, off);
            }
            l0[im] = l0[im] * corr0 + ls0;
            l1[im] = l1[im] * corr1 + ls1;
#pragma unroll
            for (int j = 0; j < 8; j++) {
                oacc[im][j][0] *= corr0; oacc[im][j][1] *= corr0;
                oacc[im][j][2] *= corr1; oacc[im][j][3] *= corr1;
            }
        }
        __syncwarp();

        // ---- O += P V ----
#pragma unroll
        for (int ks = 0; ks < 4; ks++) {
            uint32_t afr[2][4];
#pragma unroll
            for (int im = 0; im < 2; im++) {
                int rowa = w * 32 + im * 16 + r + (g & 1) * 8;
                ldsm4(afr[im][0], afr[im][1], afr[im][2], afr[im][3],
                      sb + A_SP + sw128((uint32_t)(rowa * 128) +
                                        (uint32_t)((ks * 2 + (g >> 1)) << 4)));
            }
            uint32_t bfr[8][2];
#pragma unroll
            for (int idb = 0; idb < 4; idb++) {
                int rowv = ks * 16 + (g & 1) * 8 + r;
                uint32_t ck = (uint32_t)(idb * 2 + (g >> 1));
                ldsm4t(bfr[2 * idb][0], bfr[2 * idb][1], bfr[2 * idb + 1][0], bfr[2 * idb + 1][1],
                       Vs + sw128((uint32_t)(rowv * 128) + (ck << 4)));
            }
#pragma unroll
            for (int im = 0; im < 2; im++)
#pragma unroll
                for (int j = 0; j < 8; j++)
                    mma_f16(oacc[im][j], afr[im], bfr[j][0], bfr[j][1]);
        }
        __syncthreads();
    }

    // ---- write O ----
#pragma unroll
    for (int im = 0; im < 2; im++) {
        float inv0 = 1.0f / l0[im], inv1 = 1.0f / l1[im];
        int row0 = q0 + w * 32 + im * 16 + lr;
#pragma unroll
        for (int j = 0; j < 8; j++) {
            int col = h * HD + j * 8 + 2 * lc;
            *(__half2*)(o + (size_t)(b * SEQ + row0) * DIM + col) =
                __floats2half2_rn(oacc[im][j][0] * inv0, oacc[im][j][1] * inv0);
            *(__half2*)(o + (size_t)(b * SEQ + row0 + 8) * DIM + col) =
                __floats2half2_rn(oacc[im][j][2] * inv1, oacc[im][j][3] * inv1);
        }
    }
}

// ------------------- host orchestration -------------------
extern "C" void kernel_launch(void* const* d_in, const int* in_sizes, int n_in,
                              void* d_out, int out_size) {
    const float* x     = (const float*)d_in[0];
    const float* ln1_g = (const float*)d_in[1];
    const float* ln1_b = (const float*)d_in[2];
    const float* w_qkv = (const float*)d_in[3];
    const float* w_out = (const float*)d_in[4];
    const float* b_out = (const float*)d_in[5];
    const float* ln2_g = (const float*)d_in[6];
    const float* ln2_b = (const float*)d_in[7];
    const float* w1    = (const float*)d_in[8];
    const float* b1    = (const float*)d_in[9];
    const float* w2    = (const float*)d_in[10];
    const float* b2    = (const float*)d_in[11];
    float* out = (float*)d_out;

    __half *h, *qkvb, *ob, *mlpb, *wtq, *wto, *wt1, *wt2;
    cudaGetSymbolAddress((void**)&h,    g_h);
    cudaGetSymbolAddress((void**)&qkvb, g_qkv);
    cudaGetSymbolAddress((void**)&ob,   g_o);
    cudaGetSymbolAddress((void**)&mlpb, g_mlp);
    cudaGetSymbolAddress((void**)&wtq,  g_wt_qkv);
    cudaGetSymbolAddress((void**)&wto,  g_wt_out);
    cudaGetSymbolAddress((void**)&wt1,  g_wt1);
    cudaGetSymbolAddress((void**)&wt2,  g_wt2);

    cudaFuncSetAttribute(attn_mma, cudaFuncAttributeMaxDynamicSharedMemorySize, A_SMEM);
    cudaFuncSetAttribute(gemm_mma<0>, cudaFuncAttributeMaxDynamicSharedMemorySize, GM_SMEM);
    cudaFuncSetAttribute(gemm_mma<2>, cudaFuncAttributeMaxDynamicSharedMemorySize, GM_SMEM);
    cudaFuncSetAttribute(gemm_mma<3>, cudaFuncAttributeMaxDynamicSharedMemorySize, GM_SMEM);

    // pre-transpose + fp16-convert all weights (depth via grid.z)
    transpose_h<<<dim3(3 * DIM / 64, DIM / 64, DEPTH), 256>>>(w_qkv, wtq, DIM, 3 * DIM);
    transpose_h<<<dim3(DIM / 64, DIM / 64, DEPTH), 256>>>(w_out, wto, DIM, DIM);
    transpose_h<<<dim3(MLPD / 64, DIM / 64, DEPTH), 256>>>(w1, wt1, DIM, MLPD);
    transpose_h<<<dim3(DIM / 64, MLPD / 64, DEPTH), 256>>>(w2, wt2, MLPD, DIM);

    cudaMemcpyAsync(out, x, (size_t)MROWS * DIM * sizeof(float),
                    cudaMemcpyDeviceToDevice);

    for (int lyr = 0; lyr < DEPTH; lyr++) {
        // --- attention block ---
        ln_kernel<<<MROWS / 8, 256>>>(out, ln1_g + lyr * DIM, ln1_b + lyr * DIM, h);
        gemm_mma<0><<<dim3(3 * DIM / 128, MROWS / 128), 128, GM_SMEM>>>(
            h, wtq + (size_t)lyr * 3 * DIM * DIM, nullptr, nullptr,
            qkvb, DIM, 3 * DIM);
        attn_mma<<<dim3(SEQ / 128, BATCH * HEADS), 128, A_SMEM>>>(qkvb, ob);
        gemm_mma<3><<<dim3(DIM / 128, MROWS / 128), 128, GM_SMEM>>>(
            ob, wto + (size_t)lyr * DIM * DIM, b_out + lyr * DIM, out,
            out, DIM, DIM);
        // --- MLP block ---
        ln_kernel<<<MROWS / 8, 256>>>(out, ln2_g + lyr * DIM, ln2_b + lyr * DIM, h);
        gemm_mma<2><<<dim3(MLPD / 128, MROWS / 128), 128, GM_SMEM>>>(
            h, wt1 + (size_t)lyr * DIM * MLPD, b1 + (size_t)lyr * MLPD, nullptr,
            mlpb, DIM, MLPD);
        gemm_mma<3><<<dim3(DIM / 128, MROWS / 128), 128, GM_SMEM>>>(
            mlpb, wt2 + (size_t)lyr * DIM * MLPD, b2 + lyr * DIM, out,
            out, MLPD, DIM);
    }
}

// round 17
// speedup vs baseline: 1.0047x; 1.0047x over previous
#include <cuda_runtime.h>
#include <cuda_fp16.h>
#include <math.h>
#include <stdint.h>

#define BATCH 4
#define SEQ   1024
#define DIM   1024
#define HEADS 16
#define HD    64
#define MLPD  4096
#define DEPTH 4
#define MROWS (BATCH*SEQ)          // 4096
#define ATT_SCALE (1.0f/32.0f)     // DIM^-0.5

// ------------------- scratch (no allocation allowed) -------------------
__device__ __half g_h   [MROWS*DIM];
__device__ __half g_qkv [MROWS*3*DIM];
__device__ __half g_o   [MROWS*DIM];
__device__ __half g_mlp [MROWS*MLPD];
// transposed (N-major) fp16 weights
__device__ __half g_wt_qkv[DEPTH*3*DIM*DIM];
__device__ __half g_wt_out[DEPTH*DIM*DIM];
__device__ __half g_wt1   [DEPTH*MLPD*DIM];
__device__ __half g_wt2   [DEPTH*DIM*MLPD];

// ------------------- helpers -------------------
__device__ __forceinline__ uint32_t smem_u32(const void* p) {
    uint32_t a;
    asm("{ .reg .u64 t; cvta.to.shared.u64 t, %1; cvt.u32.u64 %0, t; }" : "=r"(a) : "l"(p));
    return a;
}
static __device__ __forceinline__ uint32_t sw128(uint32_t off) {
    return off ^ ((off >> 3) & 0x70);
}
__device__ __forceinline__ void ldsm4(uint32_t& d0, uint32_t& d1, uint32_t& d2,
                                      uint32_t& d3, uint32_t addr) {
    asm volatile("ldmatrix.sync.aligned.m8n8.x4.shared.b16 {%0,%1,%2,%3}, [%4];"
                 : "=r"(d0), "=r"(d1), "=r"(d2), "=r"(d3) : "r"(addr));
}
__device__ __forceinline__ void ldsm4t(uint32_t& d0, uint32_t& d1, uint32_t& d2,
                                       uint32_t& d3, uint32_t addr) {
    asm volatile("ldmatrix.sync.aligned.m8n8.x4.trans.shared.b16 {%0,%1,%2,%3}, [%4];"
                 : "=r"(d0), "=r"(d1), "=r"(d2), "=r"(d3) : "r"(addr));
}
__device__ __forceinline__ void mma_f16(float* c, const uint32_t* a,
                                        uint32_t b0, uint32_t b1) {
    asm volatile(
        "mma.sync.aligned.m16n8k16.row.col.f32.f16.f16.f32 "
        "{%0,%1,%2,%3}, {%4,%5,%6,%7}, {%8,%9}, {%0,%1,%2,%3};"
        : "+f"(c[0]), "+f"(c[1]), "+f"(c[2]), "+f"(c[3])
        : "r"(a[0]), "r"(a[1]), "r"(a[2]), "r"(a[3]), "r"(b0), "r"(b1));
}
__device__ __forceinline__ void cp_async16(uint32_t dst, const void* src) {
    asm volatile("cp.async.ca.shared.global [%0], [%1], 16;"
                 :: "r"(dst), "l"(src) : "memory");
}
#define CP_COMMIT() asm volatile("cp.async.commit_group;" ::: "memory")
#define CP_WAIT(n)  asm volatile("cp.async.wait_group %0;" :: "n"(n) : "memory")

// ------------------- LayerNorm: one warp per row --------
__global__ void ln_kernel(const float* __restrict__ x, const float* __restrict__ g,
                          const float* __restrict__ b, __half* __restrict__ out) {
    int row  = blockIdx.x * 8 + (threadIdx.x >> 5);
    int lane = threadIdx.x & 31;
    const float* xr = x + (size_t)row * DIM;

    float4 v[8];
    float s = 0.f, s2 = 0.f;
#pragma unroll
    for (int i = 0; i < 8; i++) {
        v[i] = *(const float4*)(xr + 4 * (lane + i * 32));
        s  += v[i].x + v[i].y + v[i].z + v[i].w;
        s2 += v[i].x * v[i].x + v[i].y * v[i].y + v[i].z * v[i].z + v[i].w * v[i].w;
    }
#pragma unroll
    for (int o = 16; o > 0; o >>= 1) {
        s  += __shfl_xor_sync(0xffffffffu, s,  o);
        s2 += __shfl_xor_sync(0xffffffffu, s2, o);
    }
    float mean = s * (1.0f / DIM);
    float rstd = rsqrtf(s2 * (1.0f / DIM) - mean * mean + 1e-5f);

    __half* orow = out + (size_t)row * DIM;
#pragma unroll
    for (int i = 0; i < 8; i++) {
        int c = 4 * (lane + i * 32);
        float4 gv = *(const float4*)(g + c);
        float4 bv = *(const float4*)(b + c);
        __half2 h0 = __floats2half2_rn((v[i].x - mean) * rstd * gv.x + bv.x,
                                       (v[i].y - mean) * rstd * gv.y + bv.y);
        __half2 h1 = __floats2half2_rn((v[i].z - mean) * rstd * gv.z + bv.z,
                                       (v[i].w - mean) * rstd * gv.w + bv.w);
        *(__half2*)(orow + c)     = h0;
        *(__half2*)(orow + c + 2) = h1;
    }
}

// --------- weight transpose to fp16: Wt[n][k] = h(W[k][n]) ------------------
__global__ void transpose_h(const float* __restrict__ Wb, __half* __restrict__ Wtb,
                            int K, int N) {
    __shared__ float t[64][65];
    const float* W  = Wb  + (size_t)blockIdx.z * K * N;
    __half* Wt      = Wtb + (size_t)blockIdx.z * K * N;
    int bn = blockIdx.x * 64, bk = blockIdx.y * 64;
    int tid = threadIdx.x;
    int rk = tid >> 4;
    int cn = (tid & 15) << 2;
#pragma unroll
    for (int i = 0; i < 4; i++) {
        int k = rk + i * 16;
        float4 v = *(const float4*)(W + (size_t)(bk + k) * N + bn + cn);
        t[cn + 0][k] = v.x;
        t[cn + 1][k] = v.y;
        t[cn + 2][k] = v.z;
        t[cn + 3][k] = v.w;
    }
    __syncthreads();
    int rn = tid >> 2;
    int ck = (tid & 3) << 4;
    __half hv[16];
#pragma unroll
    for (int j = 0; j < 16; j++) hv[j] = __float2half_rn(t[rn][ck + j]);
    *(float4*)(Wt + (size_t)(bn + rn) * K + bk + ck)     = *(float4*)&hv[0];
    *(float4*)(Wt + (size_t)(bn + rn) * K + bk + ck + 8) = *(float4*)&hv[8];
}

// ------------------- fp16 mma GEMM (verified champion, unchanged) ----------
#define GM_BUF 16384
#define GM_SMEM (4 * GM_BUF + 1024)

template<int EPI>  // 0 plain->half, 2 bias+gelu->half, 3 bias+residual->float
__global__ __launch_bounds__(128, 2)
void gemm_mma(const __half* __restrict__ A, const __half* __restrict__ Bt,
              const float* __restrict__ bias, const float* __restrict__ res,
              void* __restrict__ Cv, int K, int Ndim) {
    extern __shared__ char smraw[];
    uint32_t sbase = (smem_u32(smraw) + 1023u) & ~1023u;

    int tid = threadIdx.x;
    int wid = tid >> 5, lane = tid & 31;
    int wm = wid & 1, wn = wid >> 1;       // 2x2 warp grid
    int brow = blockIdx.y << 7, bcol = blockIdx.x << 7;
    int g = lane >> 3, r = lane & 7;

    float acc[4][8][4];
#pragma unroll
    for (int i = 0; i < 4; i++)
#pragma unroll
        for (int j = 0; j < 8; j++)
#pragma unroll
            for (int q = 0; q < 4; q++) acc[i][j][q] = 0.f;

    const int KT = K >> 6;
    int arow = tid >> 3, ack = tid & 7;

    auto issue_tile = [&](uint32_t dstbase, const __half* src) {
#pragma unroll
        for (int i = 0; i < 8; i++) {
            int rr = arow + i * 16;
            cp_async16(dstbase + sw128((uint32_t)(rr * 128 + (ack << 4))),
                       src + (size_t)rr * K + (ack << 3));
        }
    };

    issue_tile(sbase, A + (size_t)brow * K);
    issue_tile(sbase + 2 * GM_BUF, Bt + (size_t)bcol * K);
    CP_COMMIT();

    for (int kt = 0; kt < KT; kt++) {
        int b = kt & 1;
        uint32_t Ab_s = sbase + b * GM_BUF;
        uint32_t Bb_s = sbase + 2 * GM_BUF + b * GM_BUF;

        CP_WAIT(0);
        __syncthreads();

        if (kt + 1 < KT) {
            int nb = b ^ 1;
            issue_tile(sbase + nb * GM_BUF,
                       A + (size_t)brow * K + ((kt + 1) << 6));
            issue_tile(sbase + 2 * GM_BUF + nb * GM_BUF,
                       Bt + (size_t)bcol * K + ((kt + 1) << 6));
            CP_COMMIT();
        }

#pragma unroll
        for (int ks = 0; ks < 4; ks++) {
            uint32_t afr[4][4];
#pragma unroll
            for (int im = 0; im < 4; im++) {
                int rowa = wm * 64 + im * 16 + r + (g & 1) * 8;
                uint32_t ck = (uint32_t)(ks * 2 + (g >> 1));
                ldsm4(afr[im][0], afr[im][1], afr[im][2], afr[im][3],
                      Ab_s + sw128((uint32_t)(rowa * 128) + (ck << 4)));
            }
            uint32_t bfr[8][2];
#pragma unroll
            for (int ip = 0; ip < 4; ip++) {
                int rowb = wn * 64 + ip * 16 + (g >> 1) * 8 + r;
                uint32_t ck = (uint32_t)(ks * 2 + (g & 1));
                ldsm4(bfr[2 * ip][0], bfr[2 * ip][1], bfr[2 * ip + 1][0], bfr[2 * ip + 1][1],
                      Bb_s + sw128((uint32_t)(rowb * 128) + (ck << 4)));
            }
#pragma unroll
            for (int im = 0; im < 4; im++)
#pragma unroll
                for (int in = 0; in < 8; in++)
                    mma_f16(acc[im][in], afr[im], bfr[in][0], bfr[in][1]);
        }
    }

    int lr = lane >> 2, lc = (lane & 3) << 1;
#pragma unroll
    for (int im = 0; im < 4; im++) {
#pragma unroll
        for (int half_ = 0; half_ < 2; half_++) {
            int row = brow + wm * 64 + im * 16 + lr + half_ * 8;
            const float* Rrow = (EPI == 3) ? (res + (size_t)row * Ndim) : nullptr;
#pragma unroll
            for (int in = 0; in < 8; in++) {
                int col = bcol + wn * 64 + in * 8 + lc;
                float u0 = acc[im][in][half_ * 2 + 0];
                float u1 = acc[im][in][half_ * 2 + 1];
                if (EPI >= 2) { u0 += bias[col]; u1 += bias[col + 1]; }
                if (EPI == 2) {
                    u0 = 0.5f * u0 * (1.0f + erff(u0 * 0.70710678118654752f));
                    u1 = 0.5f * u1 * (1.0f + erff(u1 * 0.70710678118654752f));
                }
                if (EPI == 3) {
                    float* Crow = (float*)Cv + (size_t)row * Ndim;
                    *(float2*)(Crow + col) = make_float2(u0 + Rrow[col], u1 + Rrow[col + 1]);
                } else {
                    __half* Crow = (__half*)Cv + (size_t)row * Ndim;
                    *(__half2*)(Crow + col) = __floats2half2_rn(u0, u1);
                }
            }
        }
    }
}

// ------------------- fp16 tensor-core flash attention (champion) -----------
#define A_SQ  0                    // 16384
#define A_SK  16384                // 2 x 8192
#define A_SV  32768                // 2 x 8192
#define A_SP  49152                // 16384
#define A_SMEM (65536 + 1024)

__global__ __launch_bounds__(128, 2)
void attn_mma(const __half* __restrict__ qkv, __half* __restrict__ o) {
    extern __shared__ char smraw[];
    uint32_t sraw = smem_u32(smraw);
    uint32_t sb = (sraw + 1023u) & ~1023u;
    char* smb = smraw + (sb - sraw);

    int tid = threadIdx.x;
    int w = tid >> 5, lane = tid & 31;
    int g = lane >> 3, r = lane & 7;
    int lr = lane >> 2, lc = lane & 3;

    int bh = blockIdx.y;
    int b = bh >> 4, h = bh & 15;
    int q0 = blockIdx.x << 7;
    const __half* gq = qkv + (size_t)b * SEQ * 3 * DIM + h * HD;
    const __half* gk = gq + DIM;
    const __half* gv = gq + 2 * DIM;

    auto issue_kv = [&](int st, int kt) {
#pragma unroll
        for (int i = 0; i < 4; i++) {
            int idx = tid + i * 128;
            int row = idx >> 3, ck = idx & 7;
            cp_async16(sb + A_SK + st * 8192 + sw128((uint32_t)(row * 128 + (ck << 4))),
                       gk + (size_t)(kt + row) * (3 * DIM) + (ck << 3));
            cp_async16(sb + A_SV + st * 8192 + sw128((uint32_t)(row * 128 + (ck << 4))),
                       gv + (size_t)(kt + row) * (3 * DIM) + (ck << 3));
        }
    };

    // ---- Q tile 128x64h ----
#pragma unroll
    for (int i = 0; i < 8; i++) {
        int idx = tid + i * 128;
        int row = idx >> 3, ck = idx & 7;
        cp_async16(sb + A_SQ + sw128((uint32_t)(row * 128 + (ck << 4))),
                   gq + (size_t)(q0 + row) * (3 * DIM) + (ck << 3));
    }
    CP_COMMIT();
    issue_kv(0, 0);
    CP_COMMIT();

    // ---- hoist Q fragments (loop-invariant) ----
    CP_WAIT(1);
    __syncthreads();
    uint32_t qfr[4][2][4];
#pragma unroll
    for (int ks = 0; ks < 4; ks++)
#pragma unroll
        for (int im = 0; im < 2; im++) {
            int rowa = w * 32 + im * 16 + r + (g & 1) * 8;
            ldsm4(qfr[ks][im][0], qfr[ks][im][1], qfr[ks][im][2], qfr[ks][im][3],
                  sb + A_SQ + sw128((uint32_t)(rowa * 128) +
                                    (uint32_t)((ks * 2 + (g >> 1)) << 4)));
        }

    float m0[2], m1[2], l0[2], l1[2];
    float oacc[2][8][4];
#pragma unroll
    for (int im = 0; im < 2; im++) {
        m0[im] = -1e30f; m1[im] = -1e30f; l0[im] = 0.f; l1[im] = 0.f;
#pragma unroll
        for (int j = 0; j < 8; j++)
#pragma unroll
            for (int q = 0; q < 4; q++) oacc[im][j][q] = 0.f;
    }

    const int NT = SEQ / 64;
    for (int kti = 0; kti < NT; kti++) {
        int st = kti & 1;
        uint32_t Ks = sb + A_SK + st * 8192;
        uint32_t Vs = sb + A_SV + st * 8192;

        if (kti + 1 < NT) {
            issue_kv(st ^ 1, (kti + 1) * 64);
            CP_COMMIT();
            CP_WAIT(1);
        } else {
            CP_WAIT(0);
        }
        __syncthreads();

        // ---- S = Q K^T ----
        float sacc[2][8][4];
#pragma unroll
        for (int im = 0; im < 2; im++)
#pragma unroll
            for (int j = 0; j < 8; j++)
#pragma unroll
                for (int q = 0; q < 4; q++) sacc[im][j][q] = 0.f;

#pragma unroll
        for (int ks = 0; ks < 4; ks++) {
            uint32_t bfr[8][2];
#pragma unroll
            for (int ip = 0; ip < 4; ip++) {
                int rowb = ip * 16 + (g >> 1) * 8 + r;
                ldsm4(bfr[2 * ip][0], bfr[2 * ip][1], bfr[2 * ip + 1][0], bfr[2 * ip + 1][1],
                      Ks + sw128((uint32_t)(rowb * 128) +
                                 (uint32_t)((ks * 2 + (g & 1)) << 4)));
            }
#pragma unroll
            for (int im = 0; im < 2; im++)
#pragma unroll
                for (int j = 0; j < 8; j++)
                    mma_f16(sacc[im][j], qfr[ks][im], bfr[j][0], bfr[j][1]);
        }

        // ---- online softmax ----
#pragma unroll
        for (int im = 0; im < 2; im++) {
            float rm0 = -1e30f, rm1 = -1e30f;
#pragma unroll
            for (int j = 0; j < 8; j++) {
                rm0 = fmaxf(rm0, fmaxf(sacc[im][j][0], sacc[im][j][1]));
                rm1 = fmaxf(rm1, fmaxf(sacc[im][j][2], sacc[im][j][3]));
            }
            rm0 *= ATT_SCALE; rm1 *= ATT_SCALE;
#pragma unroll
            for (int off = 1; off < 4; off <<= 1) {
                rm0 = fmaxf(rm0, __shfl_xor_sync(0xffffffffu, rm0, off));
                rm1 = fmaxf(rm1, __shfl_xor_sync(0xffffffffu, rm1, off));
            }
            float nm0 = fmaxf(m0[im], rm0), nm1 = fmaxf(m1[im], rm1);
            float corr0 = __expf(m0[im] - nm0), corr1 = __expf(m1[im] - nm1);
            m0[im] = nm0; m1[im] = nm1;
            float ls0 = 0.f, ls1 = 0.f;
            int prow0 = w * 32 + im * 16 + lr;
#pragma unroll
            for (int j = 0; j < 8; j++) {
                __half2 hp0 = __floats2half2_rn(__expf(sacc[im][j][0] * ATT_SCALE - nm0),
                                                __expf(sacc[im][j][1] * ATT_SCALE - nm0));
                __half2 hp1 = __floats2half2_rn(__expf(sacc[im][j][2] * ATT_SCALE - nm1),
                                                __expf(sacc[im][j][3] * ATT_SCALE - nm1));
                float2 f0 = __half22float2(hp0), f1 = __half22float2(hp1);
                ls0 += f0.x + f0.y; ls1 += f1.x + f1.y;
                uint32_t cb = (uint32_t)((j * 8 + 2 * lc) << 1);
                *(__half2*)(smb + A_SP + sw128((uint32_t)(prow0 * 128) + cb)) = hp0;
                *(__half2*)(smb + A_SP + sw128((uint32_t)((prow0 + 8) * 128) + cb)) = hp1;
            }
#pragma unroll
            for (int off = 1; off < 4; off <<= 1) {
                ls0 += __shfl_xor_sync(0xffffffffu, ls0, off);
                ls1 += __shfl_xor_sync(0xffffffffu, ls1, off);
            }
            l0[im] = l0[im] * corr0 + ls0;
            l1[im] = l1[im] * corr1 + ls1;
#pragma unroll
            for (int j = 0; j < 8; j++) {
                oacc[im][j][0] *= corr0; oacc[im][j][1] *= corr0;
                oacc[im][j][2] *= corr1; oacc[im][j][3] *= corr1;
            }
        }
        __syncwarp();

        // ---- O += P V ----
#pragma unroll
        for (int ks = 0; ks < 4; ks++) {
            uint32_t afr[2][4];
#pragma unroll
            for (int im = 0; im < 2; im++) {
                int rowa = w * 32 + im * 16 + r + (g & 1) * 8;
                ldsm4(afr[im][0], afr[im][1], afr[im][2], afr[im][3],
                      sb + A_SP + sw128((uint32_t)(rowa * 128) +
                                        (uint32_t)((ks * 2 + (g >> 1)) << 4)));
            }
            uint32_t bfr[8][2];
#pragma unroll
            for (int idb = 0; idb < 4; idb++) {
                int rowv = ks * 16 + (g & 1) * 8 + r;
                uint32_t ck = (uint32_t)(idb * 2 + (g >> 1));
                ldsm4t(bfr[2 * idb][0], bfr[2 * idb][1], bfr[2 * idb + 1][0], bfr[2 * idb + 1][1],
                       Vs + sw128((uint32_t)(rowv * 128) + (ck << 4)));
            }
#pragma unroll
            for (int im = 0; im < 2; im++)
#pragma unroll
                for (int j = 0; j < 8; j++)
                    mma_f16(oacc[im][j], afr[im], bfr[j][0], bfr[j][1]);
        }
        __syncthreads();
    }

    // ---- write O ----
#pragma unroll
    for (int im = 0; im < 2; im++) {
        float inv0 = 1.0f / l0[im], inv1 = 1.0f / l1[im];
        int row0 = q0 + w * 32 + im * 16 + lr;
#pragma unroll
        for (int j = 0; j < 8; j++) {
            int col = h * HD + j * 8 + 2 * lc;
            *(__half2*)(o + (size_t)(b * SEQ + row0) * DIM + col) =
                __floats2half2_rn(oacc[im][j][0] * inv0, oacc[im][j][1] * inv0);
            *(__half2*)(o + (size_t)(b * SEQ + row0 + 8) * DIM + col) =
                __floats2half2_rn(oacc[im][j][2] * inv1, oacc[im][j][3] * inv1);
        }
    }
}

// ------------------- host orchestration -------------------
extern "C" void kernel_launch(void* const* d_in, const int* in_sizes, int n_in,
                              void* d_out, int out_size) {
    const float* x     = (const float*)d_in[0];
    const float* ln1_g = (const float*)d_in[1];
    const float* ln1_b = (const float*)d_in[2];
    const float* w_qkv = (const float*)d_in[3];
    const float* w_out = (const float*)d_in[4];
    const float* b_out = (const float*)d_in[5];
    const float* ln2_g = (const float*)d_in[6];
    const float* ln2_b = (const float*)d_in[7];
    const float* w1    = (const float*)d_in[8];
    const float* b1    = (const float*)d_in[9];
    const float* w2    = (const float*)d_in[10];
    const float* b2    = (const float*)d_in[11];
    float* out = (float*)d_out;

    __half *h, *qkvb, *ob, *mlpb, *wtq, *wto, *wt1, *wt2;
    cudaGetSymbolAddress((void**)&h,    g_h);
    cudaGetSymbolAddress((void**)&qkvb, g_qkv);
    cudaGetSymbolAddress((void**)&ob,   g_o);
    cudaGetSymbolAddress((void**)&mlpb, g_mlp);
    cudaGetSymbolAddress((void**)&wtq,  g_wt_qkv);
    cudaGetSymbolAddress((void**)&wto,  g_wt_out);
    cudaGetSymbolAddress((void**)&wt1,  g_wt1);
    cudaGetSymbolAddress((void**)&wt2,  g_wt2);

    cudaFuncSetAttribute(attn_mma, cudaFuncAttributeMaxDynamicSharedMemorySize, A_SMEM);
    cudaFuncSetAttribute(gemm_mma<0>, cudaFuncAttributeMaxDynamicSharedMemorySize, GM_SMEM);
    cudaFuncSetAttribute(gemm_mma<2>, cudaFuncAttributeMaxDynamicSharedMemorySize, GM_SMEM);
    cudaFuncSetAttribute(gemm_mma<3>, cudaFuncAttributeMaxDynamicSharedMemorySize, GM_SMEM);

    // pre-transpose + fp16-convert all weights (depth via grid.z)
    transpose_h<<<dim3(3 * DIM / 64, DIM / 64, DEPTH), 256>>>(w_qkv, wtq, DIM, 3 * DIM);
    transpose_h<<<dim3(DIM / 64, DIM / 64, DEPTH), 256>>>(w_out, wto, DIM, DIM);
    transpose_h<<<dim3(MLPD / 64, DIM / 64, DEPTH), 256>>>(w1, wt1, DIM, MLPD);
    transpose_h<<<dim3(DIM / 64, MLPD / 64, DEPTH), 256>>>(w2, wt2, MLPD, DIM);

    for (int lyr = 0; lyr < DEPTH; lyr++) {
        // layer 0 reads the harness input x directly; out is first WRITTEN by
        // the layer-0 attention projection (no memcpy needed).
        const float* resid = (lyr == 0) ? x : out;

        // --- attention block ---
        ln_kernel<<<MROWS / 8, 256>>>(resid, ln1_g + lyr * DIM, ln1_b + lyr * DIM, h);
        gemm_mma<0><<<dim3(3 * DIM / 128, MROWS / 128), 128, GM_SMEM>>>(
            h, wtq + (size_t)lyr * 3 * DIM * DIM, nullptr, nullptr,
            qkvb, DIM, 3 * DIM);
        attn_mma<<<dim3(SEQ / 128, BATCH * HEADS), 128, A_SMEM>>>(qkvb, ob);
        gemm_mma<3><<<dim3(DIM / 128, MROWS / 128), 128, GM_SMEM>>>(
            ob, wto + (size_t)lyr * DIM * DIM, b_out + lyr * DIM, resid,
            out, DIM, DIM);
        // --- MLP block ---
        ln_kernel<<<MROWS / 8, 256>>>(out, ln2_g + lyr * DIM, ln2_b + lyr * DIM, h);
        gemm_mma<2><<<dim3(MLPD / 128, MROWS / 128), 128, GM_SMEM>>>(
            h, wt1 + (size_t)lyr * DIM * MLPD, b1 + (size_t)lyr * MLPD, nullptr,
            mlpb, DIM, MLPD);
        gemm_mma<3><<<dim3(DIM / 128, MROWS / 128), 128, GM_SMEM>>>(
            mlpb, wt2 + (size_t)lyr * DIM * MLPD, b2 + lyr * DIM, out,
            out, MLPD, DIM);
    }
}